// round 12
// baseline (speedup 1.0000x reference)
#include <cuda_runtime.h>

#define POOL   7
#define NPIX   49
#define BATCH  2
#define NBOX   1000
#define CCH    256
#define C4     (CCH / 4)
#define ITEMS  (NPIX * C4)      // 3136 float4 items per box

typedef unsigned long long u64;

// ---- packed f32x2 helpers (sm_103a FFMA2 path, PTX-only) ----
__device__ __forceinline__ u64 ffma2(u64 a, u64 b, u64 c) {
    u64 d;
    asm("fma.rn.f32x2 %0, %1, %2, %3;" : "=l"(d) : "l"(a), "l"(b), "l"(c));
    return d;
}
__device__ __forceinline__ u64 fmul2(u64 a, u64 b) {
    u64 d;
    asm("mul.rn.f32x2 %0, %1, %2;" : "=l"(d) : "l"(a), "l"(b));
    return d;
}
__device__ __forceinline__ u64 pack2(float x) {
    u64 d;
    unsigned u = __float_as_uint(x);
    asm("mov.b64 %0, {%1, %1};" : "=l"(d) : "r"(u));
    return d;
}

// ---------------------------------------------------------------------------
// Fused kernel: one block per (box, channel-half). 4000 blocks x 256 threads.
//  - slot (stable-sort rank) computed in-block by predicate count.
//  - per-pixel params: corner indices + 4 PACKED corner weights (valid folded)
//  - hot loop: 4x LDG.128 + 8 packed FFMA2 + 1 STG.128 per float4 item.
// ---------------------------------------------------------------------------
__global__ __launch_bounds__(256, 8) void roi_kernel(
    const float* __restrict__ boxes,
    const float* __restrict__ fm0,
    const float* __restrict__ fm1,
    const float* __restrict__ fm2,
    const float* __restrict__ fm3,
    const int*   __restrict__ level,
    float*       __restrict__ out)
{
    __shared__ int4 sIdx[NPIX];        // corner base indices (16B units)
    __shared__ u64  sWt[NPIX * 4];     // packed (w,w) corner weights
    __shared__ int  sRed[8];
    __shared__ int  sSlot;

    const int blk  = blockIdx.x;              // 0..3999
    const int box  = blk >> 1;                // 0..1999
    const int half = blk & 1;                 // channel half
    const int b    = (box >= NBOX) ? 1 : 0;
    const int ii   = box - b * NBOX;          // index within batch
    const int tid  = threadIdx.x;
    const int warp = tid >> 5, lane = tid & 31;

    const int myLv = __ldg(level + box);      // 1..4

    const float* fm; int S;
    switch (myLv - 1) {
        case 0:  fm = fm0; S = 256; break;
        case 1:  fm = fm1; S = 128; break;
        case 2:  fm = fm2; S = 64;  break;
        default: fm = fm3; S = 32;  break;
    }

    // ---- slot: predicate count over this batch's 1000 levels ----
    {
        const int* lvArr = level + b * NBOX;
        int cnt = 0;
        #pragma unroll
        for (int j = tid; j < NBOX; j += 256) {
            const int lj = __ldg(lvArr + j);
            cnt += (lj < myLv) || (lj == myLv && j < ii);
        }
        #pragma unroll
        for (int d = 16; d; d >>= 1) cnt += __shfl_xor_sync(0xffffffffu, cnt, d);
        if (lane == 0) sRed[warp] = cnt;
    }

    // ---- per-pixel params (threads 0..48) ----
    if (tid < NPIX) {
        const int py = tid / POOL;
        const int px = tid - py * POOL;
        const float sm1 = (float)(S - 1);

        const float y1 = __ldg(boxes + box * 4 + 0);
        const float x1 = __ldg(boxes + box * 4 + 1);
        const float y2 = __ldg(boxes + box * 4 + 2);
        const float x2 = __ldg(boxes + box * 4 + 3);

        const float in_y = y1 * sm1 + (float)py * ((y2 - y1) * sm1 / 6.0f);
        const float in_x = x1 * sm1 + (float)px * ((x2 - x1) * sm1 / 6.0f);

        const bool valid = (in_y >= 0.0f) && (in_y <= sm1) &&
                           (in_x >= 0.0f) && (in_x <= sm1);
        const float v = valid ? 1.0f : 0.0f;

        const float fy = floorf(in_y);
        const float fx = floorf(in_x);
        const int ty = (int)fminf(fmaxf(fy, 0.0f), sm1);
        const int by = min(ty + 1, S - 1);
        const int lx = (int)fminf(fmaxf(fx, 0.0f), sm1);
        const int rx = min(lx + 1, S - 1);

        const float wy = in_y - fy, wx = in_x - fx;
        const float oy = 1.0f - wy, ox = 1.0f - wx;

        const int rowT = (b * S + ty) * S;
        const int rowB = (b * S + by) * S;
        sIdx[tid] = make_int4((rowT + lx) * C4, (rowT + rx) * C4,
                              (rowB + lx) * C4, (rowB + rx) * C4);
        sWt[tid * 4 + 0] = pack2(oy * ox * v);   // tl
        sWt[tid * 4 + 1] = pack2(oy * wx * v);   // tr
        sWt[tid * 4 + 2] = pack2(wy * ox * v);   // bl
        sWt[tid * 4 + 3] = pack2(wy * wx * v);   // br
    }
    __syncthreads();
    if (tid == 0) {
        int s = 0;
        #pragma unroll
        for (int w = 0; w < 8; ++w) s += sRed[w];
        sSlot = s;
    }
    __syncthreads();

    // View feature map / output as 16B granules of two packed f32x2
    const ulonglong2* f2 = (const ulonglong2*)fm;
    ulonglong2* o2 = (ulonglong2*)out + (size_t)(b * NBOX + sSlot) * ITEMS;

    const int c    = (tid & 31) + (half << 5);  // channel group 0..63
    const int slot = tid >> 5;                  // 0..7 (== warp id)

    #pragma unroll
    for (int k = 0; k < 6; ++k) {
        const int pix = k * 8 + slot;           // 0..47

        const int4 id = sIdx[pix];
        const ulonglong2 tl = __ldg(f2 + id.x + c);
        const ulonglong2 tr = __ldg(f2 + id.y + c);
        const ulonglong2 bl = __ldg(f2 + id.z + c);
        const ulonglong2 br = __ldg(f2 + id.w + c);

        const u64 w1 = sWt[pix * 4 + 0];
        const u64 w2 = sWt[pix * 4 + 1];
        const u64 w3 = sWt[pix * 4 + 2];
        const u64 w4 = sWt[pix * 4 + 3];

        ulonglong2 r;
        r.x = ffma2(br.x, w4, ffma2(bl.x, w3, ffma2(tr.x, w2, fmul2(tl.x, w1))));
        r.y = ffma2(br.y, w4, ffma2(bl.y, w3, ffma2(tr.y, w2, fmul2(tl.y, w1))));
        __stcs(o2 + pix * C4 + c, r);
    }

    // tail: pixel 48 (warp 0 only)
    if (slot == 0) {
        const int4 id = sIdx[48];
        const ulonglong2 tl = __ldg(f2 + id.x + c);
        const ulonglong2 tr = __ldg(f2 + id.y + c);
        const ulonglong2 bl = __ldg(f2 + id.z + c);
        const ulonglong2 br = __ldg(f2 + id.w + c);
        const u64 w1 = sWt[48 * 4 + 0];
        const u64 w2 = sWt[48 * 4 + 1];
        const u64 w3 = sWt[48 * 4 + 2];
        const u64 w4 = sWt[48 * 4 + 3];
        ulonglong2 r;
        r.x = ffma2(br.x, w4, ffma2(bl.x, w3, ffma2(tr.x, w2, fmul2(tl.x, w1))));
        r.y = ffma2(br.y, w4, ffma2(bl.y, w3, ffma2(tr.y, w2, fmul2(tl.y, w1))));
        __stcs(o2 + 48 * C4 + c, r);
    }
}

// ---------------------------------------------------------------------------
// Launch: single fused kernel.
// ---------------------------------------------------------------------------
extern "C" void kernel_launch(void* const* d_in, const int* in_sizes, int n_in,
                              void* d_out, int out_size) {
    const float* boxes = (const float*)d_in[0];
    const float* fm0   = (const float*)d_in[1];
    const float* fm1   = (const float*)d_in[2];
    const float* fm2   = (const float*)d_in[3];
    const float* fm3   = (const float*)d_in[4];
    const int*   level = (const int*)  d_in[5];
    float*       out   = (float*)d_out;

    roi_kernel<<<BATCH * NBOX * 2, 256>>>(boxes, fm0, fm1, fm2, fm3, level, out);
}